// round 5
// baseline (speedup 1.0000x reference)
#include <cuda_runtime.h>
#include <cuda_bf16.h>

#define TILE_H 16
#define TILE_W 32
#define HALO_H (TILE_H + 2)   // 18
#define HALO_W (TILE_W + 2)   // 34
#define HALO_N (HALO_H * HALO_W)   // 612
#define CCH    64
#define HH     128
#define WWD    128
#define HW     (HH * WWD)
#define NTAP   9
#define WSTRIDE 12            // 9 weights padded to 12 floats for aligned float4 loads
#define CHUNK  16
#define NCHUNK (CCH / CHUNK)  // 4

#define XS_ELEMS (CHUNK * HALO_N)            // 9792
#define WS_ELEMS (NTAP * CCH * WSTRIDE)      // 6912
#define SMEM_BYTES ((XS_ELEMS + WS_ELEMS) * 4)  // 66816 B

extern __shared__ float smem[];

// Staging with precomputed per-thread descriptors: the (smem slot, gmem offset,
// validity) pattern is identical for every channel and every chunk, so all the
// div/mod/bounds ALU is hoisted out of the hot loop entirely.
__device__ __forceinline__ void stage_chunk(float* __restrict__ xs,
                                            const float* __restrict__ xc,  // x + b*C*HW + cc0*HW
                                            int g0, int g1, int g2,
                                            bool has2, int tid)
{
    #pragma unroll 4
    for (int c = 0; c < CHUNK; ++c) {
        float v0 = 0.f, v1 = 0.f;
        if (g0 >= 0) v0 = __ldg(xc + g0);
        if (g1 >= 0) v1 = __ldg(xc + g1);
        float* s = xs + c * HALO_N;
        s[tid]       = v0;
        s[tid + 256] = v1;
        if (has2) {
            float v2 = 0.f;
            if (g2 >= 0) v2 = __ldg(xc + g2);
            s[tid + 512] = v2;
        }
        xc += HW;
    }
}

__global__ __launch_bounds__(256)
void ahpf_fused_kernel(const float* __restrict__ x,
                       const float* __restrict__ Wt,
                       const float* __restrict__ bias,
                       float* __restrict__ out)
{
    float* xs = smem;                 // [CHUNK][18][34]
    float* ws = smem + XS_ELEMS;      // [tap][c][12], k contiguous

    const int tw0 = blockIdx.x * TILE_W;
    const int th0 = blockIdx.y * TILE_H;
    const int b   = blockIdx.z;
    const int tid = threadIdx.x;

    // --- Precompute staging descriptors (3 slots/thread, reused 7x16 times) ---
    int g0, g1, g2;
    const bool has2 = tid < (HALO_N - 512);   // tid < 100
    {
        int j, r, col, gh, gw_;
        j = tid;              r = j / HALO_W; col = j - r * HALO_W;
        gh = th0 + r - 1;     gw_ = tw0 + col - 1;
        g0 = (gh >= 0 && gh < HH && gw_ >= 0 && gw_ < WWD) ? gh * WWD + gw_ : -1;
        j = tid + 256;        r = j / HALO_W; col = j - r * HALO_W;
        gh = th0 + r - 1;     gw_ = tw0 + col - 1;
        g1 = (gh >= 0 && gh < HH && gw_ >= 0 && gw_ < WWD) ? gh * WWD + gw_ : -1;
        j = tid + 512;        r = j / HALO_W; col = j - r * HALO_W;
        gh = th0 + r - 1;     gw_ = tw0 + col - 1;
        g2 = (has2 && gh >= 0 && gh < HH && gw_ >= 0 && gw_ < WWD) ? gh * WWD + gw_ : -1;
    }

    // --- Stage weights reordered: ws[(tap*64 + c)*12 + k] = W[k][c][tap] ---
    for (int i = tid; i < NTAP * CCH * NTAP; i += 256) {
        int k   = i / (CCH * NTAP);
        int rem = i - k * (CCH * NTAP);
        int c   = rem / NTAP;
        int tap = rem - c * NTAP;
        ws[(tap * CCH + c) * WSTRIDE + k] = Wt[(k * CCH + c) * NTAP + tap];
    }

    const float* xb = x + (size_t)b * CCH * HW;

    const int w   = tid & 31;        // 0..31
    const int h2  = tid >> 5;        // 0..7  -> pixel rows 2*h2, 2*h2+1
    const int gh0 = th0 + 2 * h2;
    const int gw  = tw0 + w;

    // ---------------- Conv: 9 logits for each of 2 stacked pixels ----------------
    float acc0[NTAP], acc1[NTAP];
    #pragma unroll
    for (int k = 0; k < NTAP; ++k) { float bk = bias[k]; acc0[k] = bk; acc1[k] = bk; }

    for (int ch = 0; ch < NCHUNK; ++ch) {
        stage_chunk(xs, xb + (size_t)ch * CHUNK * HW, g0, g1, g2, has2, tid);
        __syncthreads();

        #pragma unroll 2
        for (int c = 0; c < CHUNK; ++c) {
            // union of the two pixels' 3x3 neighborhoods: 4 rows x 3 cols
            const float* xr = xs + c * HALO_N + (2 * h2) * HALO_W + w;
            float xv[4][3];
            #pragma unroll
            for (int r = 0; r < 4; ++r)
                #pragma unroll
                for (int j = 0; j < 3; ++j)
                    xv[r][j] = xr[r * HALO_W + j];

            const float* wc = ws + (ch * CHUNK + c) * WSTRIDE;
            #pragma unroll
            for (int di = 0; di < 3; ++di) {
                #pragma unroll
                for (int dj = 0; dj < 3; ++dj) {
                    const float* wq = wc + ((di * 3 + dj) * CCH) * WSTRIDE;
                    const float4 w0 = *reinterpret_cast<const float4*>(wq);
                    const float4 w1 = *reinterpret_cast<const float4*>(wq + 4);
                    const float  w8 = wq[8];
                    const float a0 = xv[di][dj];
                    const float a1 = xv[di + 1][dj];
                    acc0[0] = fmaf(a0, w0.x, acc0[0]);  acc1[0] = fmaf(a1, w0.x, acc1[0]);
                    acc0[1] = fmaf(a0, w0.y, acc0[1]);  acc1[1] = fmaf(a1, w0.y, acc1[1]);
                    acc0[2] = fmaf(a0, w0.z, acc0[2]);  acc1[2] = fmaf(a1, w0.z, acc1[2]);
                    acc0[3] = fmaf(a0, w0.w, acc0[3]);  acc1[3] = fmaf(a1, w0.w, acc1[3]);
                    acc0[4] = fmaf(a0, w1.x, acc0[4]);  acc1[4] = fmaf(a1, w1.x, acc1[4]);
                    acc0[5] = fmaf(a0, w1.y, acc0[5]);  acc1[5] = fmaf(a1, w1.y, acc1[5]);
                    acc0[6] = fmaf(a0, w1.z, acc0[6]);  acc1[6] = fmaf(a1, w1.z, acc1[6]);
                    acc0[7] = fmaf(a0, w1.w, acc0[7]);  acc1[7] = fmaf(a1, w1.w, acc1[7]);
                    acc0[8] = fmaf(a0, w8,   acc0[8]);  acc1[8] = fmaf(a1, w8,   acc1[8]);
                }
            }
        }
        if (ch != NCHUNK - 1) __syncthreads();   // last chunk stays resident for carafe
    }

    // ---------------- softmax * hamming, renormalized (denominator cancels) -----
    const float hamv[NTAP] = {0.0064f, 0.08f, 0.0064f,
                              0.08f,   1.0f,  0.08f,
                              0.0064f, 0.08f, 0.0064f};
    float mask0[NTAP], mask1[NTAP];
    {
        float mx0 = acc0[0], mx1 = acc1[0];
        #pragma unroll
        for (int k = 1; k < NTAP; ++k) { mx0 = fmaxf(mx0, acc0[k]); mx1 = fmaxf(mx1, acc1[k]); }
        float s0 = 0.f, s1 = 0.f;
        #pragma unroll
        for (int k = 0; k < NTAP; ++k) {
            float e0 = __expf(acc0[k] - mx0) * hamv[k];
            float e1 = __expf(acc1[k] - mx1) * hamv[k];
            mask0[k] = e0; mask1[k] = e1;
            s0 += e0; s1 += e1;
        }
        const float i0 = __fdividef(1.f, s0);
        const float i1 = __fdividef(1.f, s1);
        #pragma unroll
        for (int k = 0; k < NTAP; ++k) { mask0[k] *= i0; mask1[k] *= i1; }
    }

    // ---------------- reflect-padded offsets (shared by the pixel pair) ---------
    int roff[4], coff[3];
    #pragma unroll
    for (int i = 0; i < 4; ++i) {
        int g = gh0 - 1 + i;
        g = (g < 0) ? 1 : ((g >= HH) ? (HH - 2) : g);
        roff[i] = (g - th0 + 1) * HALO_W;
    }
    #pragma unroll
    for (int j = 0; j < 3; ++j) {
        int g = gw - 1 + j;
        g = (g < 0) ? 1 : ((g >= WWD) ? (WWD - 2) : g);
        coff[j] = g - tw0 + 1;
    }

    // ---------------- CARAFE lowpass + highpass residual ------------------------
    // Walk chunks in REVERSE: chunk NCHUNK-1 is still resident from the conv phase.
    float* outb = out + ((size_t)b * CCH) * HW + (size_t)gh0 * WWD + gw;

    for (int chr = 0; chr < NCHUNK; ++chr) {
        const int ch = NCHUNK - 1 - chr;
        if (chr != 0) {   // first iteration reuses resident chunk, no staging
            __syncthreads();
            stage_chunk(xs, xb + (size_t)ch * CHUNK * HW, g0, g1, g2, has2, tid);
            __syncthreads();
        }

        #pragma unroll 2
        for (int c = 0; c < CHUNK; ++c) {
            const float* xc = xs + c * HALO_N;
            float v[4][3];
            #pragma unroll
            for (int i = 0; i < 4; ++i)
                #pragma unroll
                for (int j = 0; j < 3; ++j)
                    v[i][j] = xc[roff[i] + coff[j]];

            // v[1][1] = center of pixel0, v[2][1] = center of pixel1 (never reflected)
            float lp0 = mask0[0] * v[0][0];
            float lp1 = mask1[0] * v[1][0];
            #pragma unroll
            for (int di = 0; di < 3; ++di)
                #pragma unroll
                for (int dj = 0; dj < 3; ++dj) {
                    if (di == 0 && dj == 0) continue;
                    lp0 = fmaf(mask0[di * 3 + dj], v[di][dj],     lp0);
                    lp1 = fmaf(mask1[di * 3 + dj], v[di + 1][dj], lp1);
                }

            const size_t co = (size_t)(ch * CHUNK + c) * HW;
            outb[co]       = 2.f * v[1][1] - lp0;
            outb[co + WWD] = 2.f * v[2][1] - lp1;
        }
    }
}

extern "C" void kernel_launch(void* const* d_in, const int* in_sizes, int n_in,
                              void* d_out, int out_size)
{
    const float* x  = (const float*)d_in[0];
    const float* Wt = (const float*)d_in[1];
    const float* bs = (const float*)d_in[2];
    float* out = (float*)d_out;

    const int B = in_sizes[0] / (CCH * HW);

    cudaFuncSetAttribute(ahpf_fused_kernel,
                         cudaFuncAttributeMaxDynamicSharedMemorySize, SMEM_BYTES);

    dim3 grid(WWD / TILE_W, HH / TILE_H, B);
    ahpf_fused_kernel<<<grid, 256, SMEM_BYTES>>>(x, Wt, bs, out);
}

// round 6
// speedup vs baseline: 1.3408x; 1.3408x over previous
#include <cuda_runtime.h>
#include <cuda_bf16.h>
#include <cstdint>

#define TILE_H 16
#define TILE_W 32
#define HALO_H (TILE_H + 2)        // 18
#define HALO_W (TILE_W + 2)        // 34
#define HALO_N (HALO_H * HALO_W)   // 612
#define CCH    64
#define HH     128
#define WWD    128
#define HW     (HH * WWD)
#define NTAP   9
#define WSTRIDE 12                 // 9 weights padded to 12 floats for aligned float4 loads
#define CHUNK  8
#define NCHUNK (CCH / CHUNK)       // 8

#define XS_ELEMS (CHUNK * HALO_N)            // 4896 per buffer
#define WS_ELEMS (NTAP * CCH * WSTRIDE)      // 6912
#define SMEM_BYTES ((2 * XS_ELEMS + WS_ELEMS) * 4)  // 66816 B

extern __shared__ float smem[];

#define CP_COMMIT() asm volatile("cp.async.commit_group;\n" ::: "memory")
#define CP_WAIT0()  asm volatile("cp.async.wait_group 0;\n" ::: "memory")

// Async staging of one 8-channel chunk. Per-thread slot descriptors (g0/g1/g2)
// are precomputed once; invalid slots zero-fill via cp.async's src-size=0 path,
// which also writes the zero halo for free.
__device__ __forceinline__ void stage_async(float* __restrict__ buf,
                                            const float* __restrict__ xc,  // chunk channel-0 plane
                                            int g0, int g1, int g2,
                                            bool has2, int tid)
{
    uint32_t sa = (uint32_t)__cvta_generic_to_shared(buf) + (uint32_t)tid * 4u;
    const int z0 = (g0 >= 0) ? 4 : 0;
    const int z1 = (g1 >= 0) ? 4 : 0;
    const int z2 = (g2 >= 0) ? 4 : 0;
    const float* b0 = xc + (g0 >= 0 ? g0 : 0);
    const float* b1 = xc + (g1 >= 0 ? g1 : 0);
    const float* b2 = xc + (g2 >= 0 ? g2 : 0);
    #pragma unroll
    for (int c = 0; c < CHUNK; ++c) {
        asm volatile("cp.async.ca.shared.global [%0], [%1], 4, %2;\n"
                     :: "r"(sa), "l"(b0), "r"(z0) : "memory");
        asm volatile("cp.async.ca.shared.global [%0], [%1], 4, %2;\n"
                     :: "r"(sa + 256u * 4u), "l"(b1), "r"(z1) : "memory");
        if (has2)
            asm volatile("cp.async.ca.shared.global [%0], [%1], 4, %2;\n"
                         :: "r"(sa + 512u * 4u), "l"(b2), "r"(z2) : "memory");
        sa += HALO_N * 4u;
        b0 += HW; b1 += HW; b2 += HW;
    }
}

__global__ __launch_bounds__(256, 2)
void ahpf_fused_kernel(const float* __restrict__ x,
                       const float* __restrict__ Wt,
                       const float* __restrict__ bias,
                       float* __restrict__ out)
{
    float* xsA = smem;                         // buffer 0: [8][612]
    float* xsB = smem + XS_ELEMS;              // buffer 1
    float* ws  = smem + 2 * XS_ELEMS;          // [tap][c][12], k contiguous
    float* xbuf[2] = { xsA, xsB };

    const int tw0 = blockIdx.x * TILE_W;
    const int th0 = blockIdx.y * TILE_H;
    const int b   = blockIdx.z;
    const int tid = threadIdx.x;

    // --- Precompute staging slot descriptors (identical for every chunk) ---
    int g0, g1, g2;
    const bool has2 = tid < (HALO_N - 512);   // tid < 100
    {
        int j, r, col, gh, gw_;
        j = tid;        r = j / HALO_W; col = j - r * HALO_W;
        gh = th0 + r - 1; gw_ = tw0 + col - 1;
        g0 = (gh >= 0 && gh < HH && gw_ >= 0 && gw_ < WWD) ? gh * WWD + gw_ : -1;
        j = tid + 256;  r = j / HALO_W; col = j - r * HALO_W;
        gh = th0 + r - 1; gw_ = tw0 + col - 1;
        g1 = (gh >= 0 && gh < HH && gw_ >= 0 && gw_ < WWD) ? gh * WWD + gw_ : -1;
        j = tid + 512;  r = j / HALO_W; col = j - r * HALO_W;
        gh = th0 + r - 1; gw_ = tw0 + col - 1;
        g2 = (has2 && gh >= 0 && gh < HH && gw_ >= 0 && gw_ < WWD) ? gh * WWD + gw_ : -1;
    }

    const float* xb = x + (size_t)b * CCH * HW;

    // --- Prologue: start chunk 0 copy, stage weights meanwhile ---
    stage_async(xbuf[0], xb, g0, g1, g2, has2, tid);
    CP_COMMIT();

    // ws[(tap*64 + c)*12 + k] = W[k][c][tap]
    for (int i = tid; i < NTAP * CCH * NTAP; i += 256) {
        int k   = i / (CCH * NTAP);
        int rem = i - k * (CCH * NTAP);
        int c   = rem / NTAP;
        int tap = rem - c * NTAP;
        ws[(tap * CCH + c) * WSTRIDE + k] = Wt[(k * CCH + c) * NTAP + tap];
    }

    const int w   = tid & 31;
    const int h2  = tid >> 5;            // pixel rows 2*h2, 2*h2+1
    const int gh0 = th0 + 2 * h2;
    const int gw  = tw0 + w;

    float acc0[NTAP], acc1[NTAP];
    #pragma unroll
    for (int k = 0; k < NTAP; ++k) { float bk = bias[k]; acc0[k] = bk; acc1[k] = bk; }

    CP_WAIT0();
    __syncthreads();

    // ---------------- Conv: 9 logits for each of 2 stacked pixels ----------------
    for (int ch = 0; ch < NCHUNK; ++ch) {
        if (ch + 1 < NCHUNK) {   // stream next chunk into the other buffer
            stage_async(xbuf[(ch + 1) & 1], xb + (size_t)(ch + 1) * CHUNK * HW,
                        g0, g1, g2, has2, tid);
            CP_COMMIT();
        }

        const float* xsc = xbuf[ch & 1];
        #pragma unroll 2
        for (int c = 0; c < CHUNK; ++c) {
            const float* xr = xsc + c * HALO_N + (2 * h2) * HALO_W + w;
            float xv[4][3];
            #pragma unroll
            for (int r = 0; r < 4; ++r)
                #pragma unroll
                for (int j = 0; j < 3; ++j)
                    xv[r][j] = xr[r * HALO_W + j];

            const float* wc = ws + (ch * CHUNK + c) * WSTRIDE;
            #pragma unroll
            for (int di = 0; di < 3; ++di) {
                #pragma unroll
                for (int dj = 0; dj < 3; ++dj) {
                    const float* wq = wc + ((di * 3 + dj) * CCH) * WSTRIDE;
                    const float4 w0 = *reinterpret_cast<const float4*>(wq);
                    const float4 w1 = *reinterpret_cast<const float4*>(wq + 4);
                    const float  w8 = wq[8];
                    const float a0 = xv[di][dj];
                    const float a1 = xv[di + 1][dj];
                    acc0[0] = fmaf(a0, w0.x, acc0[0]);  acc1[0] = fmaf(a1, w0.x, acc1[0]);
                    acc0[1] = fmaf(a0, w0.y, acc0[1]);  acc1[1] = fmaf(a1, w0.y, acc1[1]);
                    acc0[2] = fmaf(a0, w0.z, acc0[2]);  acc1[2] = fmaf(a1, w0.z, acc1[2]);
                    acc0[3] = fmaf(a0, w0.w, acc0[3]);  acc1[3] = fmaf(a1, w0.w, acc1[3]);
                    acc0[4] = fmaf(a0, w1.x, acc0[4]);  acc1[4] = fmaf(a1, w1.x, acc1[4]);
                    acc0[5] = fmaf(a0, w1.y, acc0[5]);  acc1[5] = fmaf(a1, w1.y, acc1[5]);
                    acc0[6] = fmaf(a0, w1.z, acc0[6]);  acc1[6] = fmaf(a1, w1.z, acc1[6]);
                    acc0[7] = fmaf(a0, w1.w, acc0[7]);  acc1[7] = fmaf(a1, w1.w, acc1[7]);
                    acc0[8] = fmaf(a0, w8,   acc0[8]);  acc1[8] = fmaf(a1, w8,   acc1[8]);
                }
            }
        }

        if (ch + 1 < NCHUNK) CP_WAIT0();   // copies long finished under compute
        __syncthreads();
    }

    // ---------------- softmax * hamming, renormalized (denominator cancels) -----
    const float hamv[NTAP] = {0.0064f, 0.08f, 0.0064f,
                              0.08f,   1.0f,  0.08f,
                              0.0064f, 0.08f, 0.0064f};
    float mask0[NTAP], mask1[NTAP];
    {
        float mx0 = acc0[0], mx1 = acc1[0];
        #pragma unroll
        for (int k = 1; k < NTAP; ++k) { mx0 = fmaxf(mx0, acc0[k]); mx1 = fmaxf(mx1, acc1[k]); }
        float s0 = 0.f, s1 = 0.f;
        #pragma unroll
        for (int k = 0; k < NTAP; ++k) {
            float e0 = __expf(acc0[k] - mx0) * hamv[k];
            float e1 = __expf(acc1[k] - mx1) * hamv[k];
            mask0[k] = e0; mask1[k] = e1;
            s0 += e0; s1 += e1;
        }
        const float i0 = __fdividef(1.f, s0);
        const float i1 = __fdividef(1.f, s1);
        #pragma unroll
        for (int k = 0; k < NTAP; ++k) { mask0[k] *= i0; mask1[k] *= i1; }
    }

    // ---------------- reflect-padded offsets (shared by the pixel pair) ---------
    int roff[4], coff[3];
    #pragma unroll
    for (int i = 0; i < 4; ++i) {
        int g = gh0 - 1 + i;
        g = (g < 0) ? 1 : ((g >= HH) ? (HH - 2) : g);
        roff[i] = (g - th0 + 1) * HALO_W;
    }
    #pragma unroll
    for (int j = 0; j < 3; ++j) {
        int g = gw - 1 + j;
        g = (g < 0) ? 1 : ((g >= WWD) ? (WWD - 2) : g);
        coff[j] = g - tw0 + 1;
    }

    // ---------------- CARAFE lowpass + highpass residual ------------------------
    // Reverse walk: chunk NCHUNK-1 is still resident in buf[(NCHUNK-1)&1].
    float* outb = out + ((size_t)b * CCH) * HW + (size_t)gh0 * WWD + gw;

    for (int chr = 0; chr < NCHUNK; ++chr) {
        const int ch = NCHUNK - 1 - chr;
        if (ch > 0) {   // stream previous chunk into the other buffer
            stage_async(xbuf[(ch - 1) & 1], xb + (size_t)(ch - 1) * CHUNK * HW,
                        g0, g1, g2, has2, tid);
            CP_COMMIT();
        }

        const float* xsc = xbuf[ch & 1];
        #pragma unroll 2
        for (int c = 0; c < CHUNK; ++c) {
            const float* xc = xsc + c * HALO_N;
            float v[4][3];
            #pragma unroll
            for (int i = 0; i < 4; ++i)
                #pragma unroll
                for (int j = 0; j < 3; ++j)
                    v[i][j] = xc[roff[i] + coff[j]];

            // v[1][1] = center of pixel0, v[2][1] = center of pixel1 (never reflected)
            float lp0 = mask0[0] * v[0][0];
            float lp1 = mask1[0] * v[1][0];
            #pragma unroll
            for (int di = 0; di < 3; ++di)
                #pragma unroll
                for (int dj = 0; dj < 3; ++dj) {
                    if (di == 0 && dj == 0) continue;
                    lp0 = fmaf(mask0[di * 3 + dj], v[di][dj],     lp0);
                    lp1 = fmaf(mask1[di * 3 + dj], v[di + 1][dj], lp1);
                }

            const size_t co = (size_t)(ch * CHUNK + c) * HW;
            outb[co]       = 2.f * v[1][1] - lp0;
            outb[co + WWD] = 2.f * v[2][1] - lp1;
        }

        if (ch > 0) {
            CP_WAIT0();
            __syncthreads();
        }
    }
}

extern "C" void kernel_launch(void* const* d_in, const int* in_sizes, int n_in,
                              void* d_out, int out_size)
{
    const float* x  = (const float*)d_in[0];
    const float* Wt = (const float*)d_in[1];
    const float* bs = (const float*)d_in[2];
    float* out = (float*)d_out;

    const int B = in_sizes[0] / (CCH * HW);

    cudaFuncSetAttribute(ahpf_fused_kernel,
                         cudaFuncAttributeMaxDynamicSharedMemorySize, SMEM_BYTES);

    dim3 grid(WWD / TILE_W, HH / TILE_H, B);
    ahpf_fused_kernel<<<grid, 256, SMEM_BYTES>>>(x, Wt, bs, out);
}

// round 7
// speedup vs baseline: 1.3830x; 1.0315x over previous
#include <cuda_runtime.h>
#include <cuda_bf16.h>
#include <cstdint>

#define TILE_H 16
#define TILE_W 32
#define HALO_H (TILE_H + 2)        // 18
#define ROWSPAN 40                 // padded row: gmem cols [tw0-4, tw0+36), 160B aligned
#define PLANE  (HALO_H * ROWSPAN)  // 720 floats per channel plane
#define CCH    64
#define HH     128
#define WWD    128
#define HW     (HH * WWD)
#define NTAP   9
#define WSTRIDE 12                 // 9 weights padded to 12 floats for aligned float4 loads
#define CHUNK  8
#define NCHUNK (CCH / CHUNK)       // 8
#define NSLOT4 (CHUNK * HALO_H * 10)   // 1440 float4 slots per chunk staging

#define XS_ELEMS (CHUNK * PLANE)             // 5760 floats per buffer
#define WS_ELEMS (NTAP * CCH * WSTRIDE)      // 6912
#define SMEM_BYTES ((2 * XS_ELEMS + WS_ELEMS) * 4)  // 73728 B -> 2 CTA/SM

extern __shared__ float smem[];

#define CP_COMMIT() asm volatile("cp.async.commit_group;\n" ::: "memory")
#define CP_WAIT0()  asm volatile("cp.async.wait_group 0;\n" ::: "memory")

// One 8-channel chunk = 1440 aligned float4 copies; 6 slots/thread, descriptors
// (gmem float-offset, validity) precomputed once. Invalid slots zero-fill via
// cp.async src-size=0, which also writes the conv's zero halo at image borders.
__device__ __forceinline__ void stage_async(float* __restrict__ buf,
                                            const float* __restrict__ xc,  // chunk channel-0 plane
                                            const int* __restrict__ goff,
                                            int tid)
{
    uint32_t sa = (uint32_t)__cvta_generic_to_shared(buf) + (uint32_t)tid * 16u;
    #pragma unroll
    for (int s = 0; s < 5; ++s) {
        const int o = goff[s];
        const float* src = xc + (o >= 0 ? o : 0);
        const int z = (o >= 0) ? 16 : 0;
        asm volatile("cp.async.cg.shared.global [%0], [%1], 16, %2;\n"
                     :: "r"(sa + (uint32_t)s * 4096u), "l"(src), "r"(z) : "memory");
    }
    if (tid < (NSLOT4 - 5 * 256)) {   // tid < 160
        const int o = goff[5];
        const float* src = xc + (o >= 0 ? o : 0);
        const int z = (o >= 0) ? 16 : 0;
        asm volatile("cp.async.cg.shared.global [%0], [%1], 16, %2;\n"
                     :: "r"(sa + 5u * 4096u), "l"(src), "r"(z) : "memory");
    }
}

__global__ __launch_bounds__(256, 2)
void ahpf_fused_kernel(const float* __restrict__ x,
                       const float* __restrict__ Wt,
                       const float* __restrict__ bias,
                       float* __restrict__ out)
{
    float* xsA = smem;                         // buffer 0: [8][18][40]
    float* xsB = smem + XS_ELEMS;              // buffer 1
    float* ws  = smem + 2 * XS_ELEMS;          // [tap][c][12], k contiguous
    float* xbuf[2] = { xsA, xsB };

    const int tw0 = blockIdx.x * TILE_W;
    const int th0 = blockIdx.y * TILE_H;
    const int b   = blockIdx.z;
    const int tid = threadIdx.x;

    // --- Precompute float4 staging descriptors (6 slots/thread, reused 15x) ---
    int goff[6];
    #pragma unroll
    for (int s = 0; s < 6; ++s) {
        const int i = tid + 256 * s;
        int o = -1;
        if (i < NSLOT4) {
            const int chan = i / 180;          // 180 float4 per channel plane
            const int p    = i - chan * 180;
            const int r    = p / 10;           // halo row 0..17
            const int g    = p - r * 10;       // 4-col group 0..9
            const int row  = th0 - 1 + r;
            const int col  = tw0 - 4 + 4 * g;  // group fully in or out (4 | tw0)
            if (row >= 0 && row < HH && col >= 0 && col < WWD)
                o = chan * HW + row * WWD + col;
        }
        goff[s] = o;
    }

    const float* xb = x + (size_t)b * CCH * HW;

    // --- Prologue: start chunk 0 copy, stage weights meanwhile ---
    stage_async(xbuf[0], xb, goff, tid);
    CP_COMMIT();

    // ws[(tap*64 + c)*12 + k] = W[k][c][tap]
    for (int i = tid; i < NTAP * CCH * NTAP; i += 256) {
        int k   = i / (CCH * NTAP);
        int rem = i - k * (CCH * NTAP);
        int c   = rem / NTAP;
        int tap = rem - c * NTAP;
        ws[(tap * CCH + c) * WSTRIDE + k] = Wt[(k * CCH + c) * NTAP + tap];
    }

    const int w   = tid & 31;
    const int h2  = tid >> 5;            // pixel rows 2*h2, 2*h2+1
    const int gh0 = th0 + 2 * h2;
    const int gw  = tw0 + w;

    float acc0[NTAP], acc1[NTAP];
    #pragma unroll
    for (int k = 0; k < NTAP; ++k) { float bk = bias[k]; acc0[k] = bk; acc1[k] = bk; }

    CP_WAIT0();
    __syncthreads();

    // ---------------- Conv: 9 logits for each of 2 stacked pixels ----------------
    for (int ch = 0; ch < NCHUNK; ++ch) {
        if (ch + 1 < NCHUNK) {   // stream next chunk into the other buffer
            stage_async(xbuf[(ch + 1) & 1], xb + (size_t)(ch + 1) * CHUNK * HW, goff, tid);
            CP_COMMIT();
        }

        const float* xsc = xbuf[ch & 1];
        #pragma unroll 2
        for (int c = 0; c < CHUNK; ++c) {
            // union of the two pixels' 3x3 neighborhoods: 4 rows x 3 cols
            const float* xr = xsc + c * PLANE + (2 * h2) * ROWSPAN + (w + 3);
            float xv[4][3];
            #pragma unroll
            for (int r = 0; r < 4; ++r)
                #pragma unroll
                for (int j = 0; j < 3; ++j)
                    xv[r][j] = xr[r * ROWSPAN + j];

            const float* wc = ws + (ch * CHUNK + c) * WSTRIDE;
            #pragma unroll
            for (int di = 0; di < 3; ++di) {
                #pragma unroll
                for (int dj = 0; dj < 3; ++dj) {
                    const float* wq = wc + ((di * 3 + dj) * CCH) * WSTRIDE;
                    const float4 w0 = *reinterpret_cast<const float4*>(wq);
                    const float4 w1 = *reinterpret_cast<const float4*>(wq + 4);
                    const float  w8 = wq[8];
                    const float a0 = xv[di][dj];
                    const float a1 = xv[di + 1][dj];
                    acc0[0] = fmaf(a0, w0.x, acc0[0]);  acc1[0] = fmaf(a1, w0.x, acc1[0]);
                    acc0[1] = fmaf(a0, w0.y, acc0[1]);  acc1[1] = fmaf(a1, w0.y, acc1[1]);
                    acc0[2] = fmaf(a0, w0.z, acc0[2]);  acc1[2] = fmaf(a1, w0.z, acc1[2]);
                    acc0[3] = fmaf(a0, w0.w, acc0[3]);  acc1[3] = fmaf(a1, w0.w, acc1[3]);
                    acc0[4] = fmaf(a0, w1.x, acc0[4]);  acc1[4] = fmaf(a1, w1.x, acc1[4]);
                    acc0[5] = fmaf(a0, w1.y, acc0[5]);  acc1[5] = fmaf(a1, w1.y, acc1[5]);
                    acc0[6] = fmaf(a0, w1.z, acc0[6]);  acc1[6] = fmaf(a1, w1.z, acc1[6]);
                    acc0[7] = fmaf(a0, w1.w, acc0[7]);  acc1[7] = fmaf(a1, w1.w, acc1[7]);
                    acc0[8] = fmaf(a0, w8,   acc0[8]);  acc1[8] = fmaf(a1, w8,   acc1[8]);
                }
            }
        }

        if (ch + 1 < NCHUNK) CP_WAIT0();   // copies long finished under compute
        __syncthreads();
    }

    // ---------------- softmax * hamming, renormalized (denominator cancels) -----
    const float hamv[NTAP] = {0.0064f, 0.08f, 0.0064f,
                              0.08f,   1.0f,  0.08f,
                              0.0064f, 0.08f, 0.0064f};
    float mask0[NTAP], mask1[NTAP];
    {
        float mx0 = acc0[0], mx1 = acc1[0];
        #pragma unroll
        for (int k = 1; k < NTAP; ++k) { mx0 = fmaxf(mx0, acc0[k]); mx1 = fmaxf(mx1, acc1[k]); }
        float s0 = 0.f, s1 = 0.f;
        #pragma unroll
        for (int k = 0; k < NTAP; ++k) {
            float e0 = __expf(acc0[k] - mx0) * hamv[k];
            float e1 = __expf(acc1[k] - mx1) * hamv[k];
            mask0[k] = e0; mask1[k] = e1;
            s0 += e0; s1 += e1;
        }
        const float i0 = __fdividef(1.f, s0);
        const float i1 = __fdividef(1.f, s1);
        #pragma unroll
        for (int k = 0; k < NTAP; ++k) { mask0[k] *= i0; mask1[k] *= i1; }
    }

    // ---------------- reflect-padded offsets (shared by the pixel pair) ---------
    int roff[4], coff[3];
    #pragma unroll
    for (int i = 0; i < 4; ++i) {
        int g = gh0 - 1 + i;
        g = (g < 0) ? 1 : ((g >= HH) ? (HH - 2) : g);
        roff[i] = (g - th0 + 1) * ROWSPAN;
    }
    #pragma unroll
    for (int j = 0; j < 3; ++j) {
        int g = gw - 1 + j;
        g = (g < 0) ? 1 : ((g >= WWD) ? (WWD - 2) : g);
        coff[j] = g - tw0 + 4;
    }

    // ---------------- CARAFE lowpass + highpass residual ------------------------
    // Reverse walk: chunk NCHUNK-1 is still resident in buf[(NCHUNK-1)&1].
    float* outb = out + ((size_t)b * CCH) * HW + (size_t)gh0 * WWD + gw;

    for (int chr = 0; chr < NCHUNK; ++chr) {
        const int ch = NCHUNK - 1 - chr;
        if (ch > 0) {   // stream previous chunk into the other buffer
            stage_async(xbuf[(ch - 1) & 1], xb + (size_t)(ch - 1) * CHUNK * HW, goff, tid);
            CP_COMMIT();
        }

        const float* xsc = xbuf[ch & 1];
        #pragma unroll 2
        for (int c = 0; c < CHUNK; ++c) {
            const float* xc = xsc + c * PLANE;
            float v[4][3];
            #pragma unroll
            for (int i = 0; i < 4; ++i)
                #pragma unroll
                for (int j = 0; j < 3; ++j)
                    v[i][j] = xc[roff[i] + coff[j]];

            // v[1][1] = center of pixel0, v[2][1] = center of pixel1 (never reflected)
            float lp0 = mask0[0] * v[0][0];
            float lp1 = mask1[0] * v[1][0];
            #pragma unroll
            for (int di = 0; di < 3; ++di)
                #pragma unroll
                for (int dj = 0; dj < 3; ++dj) {
                    if (di == 0 && dj == 0) continue;
                    lp0 = fmaf(mask0[di * 3 + dj], v[di][dj],     lp0);
                    lp1 = fmaf(mask1[di * 3 + dj], v[di + 1][dj], lp1);
                }

            const size_t co = (size_t)(ch * CHUNK + c) * HW;
            outb[co]       = 2.f * v[1][1] - lp0;
            outb[co + WWD] = 2.f * v[2][1] - lp1;
        }

        if (ch > 0) {
            CP_WAIT0();
            __syncthreads();
        }
    }
}

extern "C" void kernel_launch(void* const* d_in, const int* in_sizes, int n_in,
                              void* d_out, int out_size)
{
    const float* x  = (const float*)d_in[0];
    const float* Wt = (const float*)d_in[1];
    const float* bs = (const float*)d_in[2];
    float* out = (float*)d_out;

    const int B = in_sizes[0] / (CCH * HW);

    cudaFuncSetAttribute(ahpf_fused_kernel,
                         cudaFuncAttributeMaxDynamicSharedMemorySize, SMEM_BYTES);

    dim3 grid(WWD / TILE_W, HH / TILE_H, B);
    ahpf_fused_kernel<<<grid, 256, SMEM_BYTES>>>(x, Wt, bs, out);
}

// round 8
// speedup vs baseline: 1.3927x; 1.0070x over previous
#include <cuda_runtime.h>
#include <cuda_bf16.h>
#include <cstdint>

#define TILE_H 16
#define TILE_W 32
#define HALO_H (TILE_H + 2)        // 18
#define ROWSPAN 40                 // padded row: gmem cols [tw0-4, tw0+36), 160B aligned
#define PLANE  (HALO_H * ROWSPAN)  // 720 floats per channel plane
#define CCH    64
#define HH     128
#define WWD    128
#define HW     (HH * WWD)
#define NTAP   9
#define WSTRIDE 12                 // 9 weights padded to 12 floats for aligned 16B loads
#define CHUNK  8
#define NCHUNK (CCH / CHUNK)       // 8
#define NSLOT4 (CHUNK * HALO_H * 10)   // 1440 float4 slots per chunk staging

#define XS_ELEMS (CHUNK * PLANE)             // 5760 floats per buffer
#define WS_ELEMS (NTAP * CCH * WSTRIDE)      // 6912
#define SMEM_BYTES ((2 * XS_ELEMS + WS_ELEMS) * 4)  // 73728 B -> 2 CTA/SM

extern __shared__ float smem[];

typedef unsigned long long u64t;

#define CP_COMMIT() asm volatile("cp.async.commit_group;\n" ::: "memory")
#define CP_WAIT0()  asm volatile("cp.async.wait_group 0;\n" ::: "memory")

__device__ __forceinline__ u64t pack2(float lo, float hi) {
    u64t r;
    asm("mov.b64 %0, {%1, %2};" : "=l"(r) : "r"(__float_as_uint(lo)), "r"(__float_as_uint(hi)));
    return r;
}
__device__ __forceinline__ u64t dup2(float v) {
    u64t r;
    asm("mov.b64 %0, {%1, %1};" : "=l"(r) : "r"(__float_as_uint(v)));
    return r;
}
// d = a*b + c elementwise on packed f32x2 -> single FFMA2 in SASS
__device__ __forceinline__ u64t ffma2(u64t a, u64t b, u64t c) {
    u64t d;
    asm("fma.rn.f32x2 %0, %1, %2, %3;" : "=l"(d) : "l"(a), "l"(b), "l"(c));
    return d;
}

// One 8-channel chunk = 1440 aligned float4 copies; 6 slots/thread, descriptors
// precomputed once. Invalid slots zero-fill via cp.async src-size=0, which also
// writes the conv's zero halo at image borders.
__device__ __forceinline__ void stage_async(float* __restrict__ buf,
                                            const float* __restrict__ xc,
                                            const int* __restrict__ goff,
                                            int tid)
{
    uint32_t sa = (uint32_t)__cvta_generic_to_shared(buf) + (uint32_t)tid * 16u;
    #pragma unroll
    for (int s = 0; s < 5; ++s) {
        const int o = goff[s];
        const float* src = xc + (o >= 0 ? o : 0);
        const int z = (o >= 0) ? 16 : 0;
        asm volatile("cp.async.cg.shared.global [%0], [%1], 16, %2;\n"
                     :: "r"(sa + (uint32_t)s * 4096u), "l"(src), "r"(z) : "memory");
    }
    if (tid < (NSLOT4 - 5 * 256)) {   // tid < 160
        const int o = goff[5];
        const float* src = xc + (o >= 0 ? o : 0);
        const int z = (o >= 0) ? 16 : 0;
        asm volatile("cp.async.cg.shared.global [%0], [%1], 16, %2;\n"
                     :: "r"(sa + 5u * 4096u), "l"(src), "r"(z) : "memory");
    }
}

__global__ __launch_bounds__(256, 2)
void ahpf_fused_kernel(const float* __restrict__ x,
                       const float* __restrict__ Wt,
                       const float* __restrict__ bias,
                       float* __restrict__ out)
{
    float* xsA = smem;                         // buffer 0: [8][18][40]
    float* xsB = smem + XS_ELEMS;              // buffer 1
    float* ws  = smem + 2 * XS_ELEMS;          // [tap][c][12], k contiguous
    float* xbuf[2] = { xsA, xsB };

    const int tw0 = blockIdx.x * TILE_W;
    const int th0 = blockIdx.y * TILE_H;
    const int b   = blockIdx.z;
    const int tid = threadIdx.x;

    // --- Precompute float4 staging descriptors (6 slots/thread, reused 15x) ---
    int goff[6];
    #pragma unroll
    for (int s = 0; s < 6; ++s) {
        const int i = tid + 256 * s;
        int o = -1;
        if (i < NSLOT4) {
            const int chan = i / 180;          // 180 float4 per channel plane
            const int p    = i - chan * 180;
            const int r    = p / 10;           // halo row 0..17
            const int g    = p - r * 10;       // 4-col group 0..9
            const int row  = th0 - 1 + r;
            const int col  = tw0 - 4 + 4 * g;  // group fully in or out (4 | tw0)
            if (row >= 0 && row < HH && col >= 0 && col < WWD)
                o = chan * HW + row * WWD + col;
        }
        goff[s] = o;
    }

    const float* xb = x + (size_t)b * CCH * HW;

    // --- Prologue: start chunk 0 copy, stage weights meanwhile ---
    stage_async(xbuf[0], xb, goff, tid);
    CP_COMMIT();

    // ws[(tap*64 + c)*12 + k] = W[k][c][tap]
    for (int i = tid; i < NTAP * CCH * NTAP; i += 256) {
        int k   = i / (CCH * NTAP);
        int rem = i - k * (CCH * NTAP);
        int c   = rem / NTAP;
        int tap = rem - c * NTAP;
        ws[(tap * CCH + c) * WSTRIDE + k] = Wt[(k * CCH + c) * NTAP + tap];
    }

    const int w   = tid & 31;
    const int h2  = tid >> 5;            // pixel rows 2*h2, 2*h2+1
    const int gh0 = th0 + 2 * h2;
    const int gw  = tw0 + w;

    // Packed accumulators: accA = pixel0 k-pairs (0,1)(2,3)(4,5)(6,7), acc8a = k=8
    u64t accA[4], accB[4];
    float acc8a, acc8b;
    #pragma unroll
    for (int j = 0; j < 4; ++j) {
        u64t bp = pack2(bias[2 * j], bias[2 * j + 1]);
        accA[j] = bp; accB[j] = bp;
    }
    acc8a = bias[8]; acc8b = acc8a;

    CP_WAIT0();
    __syncthreads();

    // ---------------- Conv via FFMA2: 9 logits for each of 2 stacked pixels ------
    for (int ch = 0; ch < NCHUNK; ++ch) {
        if (ch + 1 < NCHUNK) {
            stage_async(xbuf[(ch + 1) & 1], xb + (size_t)(ch + 1) * CHUNK * HW, goff, tid);
            CP_COMMIT();
        }

        const float* xsc = xbuf[ch & 1];
        #pragma unroll 2
        for (int c = 0; c < CHUNK; ++c) {
            // union of the two pixels' 3x3 neighborhoods: 4 rows x 3 cols
            const float* xr = xsc + c * PLANE + (2 * h2) * ROWSPAN + (w + 3);
            float xv[4][3];
            #pragma unroll
            for (int r = 0; r < 4; ++r)
                #pragma unroll
                for (int j = 0; j < 3; ++j)
                    xv[r][j] = xr[r * ROWSPAN + j];

            const float* wc = ws + (ch * CHUNK + c) * WSTRIDE;
            #pragma unroll
            for (int di = 0; di < 3; ++di) {
                #pragma unroll
                for (int dj = 0; dj < 3; ++dj) {
                    const float* wq = wc + ((di * 3 + dj) * CCH) * WSTRIDE;
                    // one LDS.128 -> two (w_k, w_k+1) b64 pairs, straight from smem
                    const ulonglong2 wp0 = *reinterpret_cast<const ulonglong2*>(wq);
                    const ulonglong2 wp1 = *reinterpret_cast<const ulonglong2*>(wq + 4);
                    const float      w8  = wq[8];
                    const float a0 = xv[di][dj];
                    const float a1 = xv[di + 1][dj];
                    const u64t a0d = dup2(a0);
                    const u64t a1d = dup2(a1);
                    accA[0] = ffma2(a0d, wp0.x, accA[0]);
                    accA[1] = ffma2(a0d, wp0.y, accA[1]);
                    accA[2] = ffma2(a0d, wp1.x, accA[2]);
                    accA[3] = ffma2(a0d, wp1.y, accA[3]);
                    acc8a   = fmaf(a0, w8, acc8a);
                    accB[0] = ffma2(a1d, wp0.x, accB[0]);
                    accB[1] = ffma2(a1d, wp0.y, accB[1]);
                    accB[2] = ffma2(a1d, wp1.x, accB[2]);
                    accB[3] = ffma2(a1d, wp1.y, accB[3]);
                    acc8b   = fmaf(a1, w8, acc8b);
                }
            }
        }

        if (ch + 1 < NCHUNK) CP_WAIT0();
        __syncthreads();
    }

    // Unpack accumulators
    float acc0[NTAP], acc1[NTAP];
    #pragma unroll
    for (int j = 0; j < 4; ++j) {
        float2 fa = *reinterpret_cast<float2*>(&accA[j]);
        float2 fb = *reinterpret_cast<float2*>(&accB[j]);
        acc0[2 * j] = fa.x; acc0[2 * j + 1] = fa.y;
        acc1[2 * j] = fb.x; acc1[2 * j + 1] = fb.y;
    }
    acc0[8] = acc8a; acc1[8] = acc8b;

    // ---------------- softmax * hamming, renormalized (denominator cancels) -----
    const float hamv[NTAP] = {0.0064f, 0.08f, 0.0064f,
                              0.08f,   1.0f,  0.08f,
                              0.0064f, 0.08f, 0.0064f};
    float mask0[NTAP], mask1[NTAP];
    {
        float mx0 = acc0[0], mx1 = acc1[0];
        #pragma unroll
        for (int k = 1; k < NTAP; ++k) { mx0 = fmaxf(mx0, acc0[k]); mx1 = fmaxf(mx1, acc1[k]); }
        float s0 = 0.f, s1 = 0.f;
        #pragma unroll
        for (int k = 0; k < NTAP; ++k) {
            float e0 = __expf(acc0[k] - mx0) * hamv[k];
            float e1 = __expf(acc1[k] - mx1) * hamv[k];
            mask0[k] = e0; mask1[k] = e1;
            s0 += e0; s1 += e1;
        }
        const float i0 = __fdividef(1.f, s0);
        const float i1 = __fdividef(1.f, s1);
        #pragma unroll
        for (int k = 0; k < NTAP; ++k) { mask0[k] *= i0; mask1[k] *= i1; }
    }

    // ---------------- reflect-padded offsets (shared by the pixel pair) ---------
    int roff[4], coff[3];
    #pragma unroll
    for (int i = 0; i < 4; ++i) {
        int g = gh0 - 1 + i;
        g = (g < 0) ? 1 : ((g >= HH) ? (HH - 2) : g);
        roff[i] = (g - th0 + 1) * ROWSPAN;
    }
    #pragma unroll
    for (int j = 0; j < 3; ++j) {
        int g = gw - 1 + j;
        g = (g < 0) ? 1 : ((g >= WWD) ? (WWD - 2) : g);
        coff[j] = g - tw0 + 4;
    }

    // ---------------- CARAFE lowpass + highpass residual ------------------------
    // Reverse walk: chunk NCHUNK-1 is still resident in buf[(NCHUNK-1)&1].
    float* outb = out + ((size_t)b * CCH) * HW + (size_t)gh0 * WWD + gw;

    for (int chr = 0; chr < NCHUNK; ++chr) {
        const int ch = NCHUNK - 1 - chr;
        if (ch > 0) {
            stage_async(xbuf[(ch - 1) & 1], xb + (size_t)(ch - 1) * CHUNK * HW, goff, tid);
            CP_COMMIT();
        }

        const float* xsc = xbuf[ch & 1];
        #pragma unroll 2
        for (int c = 0; c < CHUNK; ++c) {
            const float* xc = xsc + c * PLANE;
            float v[4][3];
            #pragma unroll
            for (int i = 0; i < 4; ++i)
                #pragma unroll
                for (int j = 0; j < 3; ++j)
                    v[i][j] = xc[roff[i] + coff[j]];

            // v[1][1] = center of pixel0, v[2][1] = center of pixel1 (never reflected)
            float lp0 = mask0[0] * v[0][0];
            float lp1 = mask1[0] * v[1][0];
            #pragma unroll
            for (int di = 0; di < 3; ++di)
                #pragma unroll
                for (int dj = 0; dj < 3; ++dj) {
                    if (di == 0 && dj == 0) continue;
                    lp0 = fmaf(mask0[di * 3 + dj], v[di][dj],     lp0);
                    lp1 = fmaf(mask1[di * 3 + dj], v[di + 1][dj], lp1);
                }

            const size_t co = (size_t)(ch * CHUNK + c) * HW;
            outb[co]       = 2.f * v[1][1] - lp0;
            outb[co + WWD] = 2.f * v[2][1] - lp1;
        }

        if (ch > 0) {
            CP_WAIT0();
            __syncthreads();
        }
    }
}

extern "C" void kernel_launch(void* const* d_in, const int* in_sizes, int n_in,
                              void* d_out, int out_size)
{
    const float* x  = (const float*)d_in[0];
    const float* Wt = (const float*)d_in[1];
    const float* bs = (const float*)d_in[2];
    float* out = (float*)d_out;

    const int B = in_sizes[0] / (CCH * HW);

    cudaFuncSetAttribute(ahpf_fused_kernel,
                         cudaFuncAttributeMaxDynamicSharedMemorySize, SMEM_BYTES);

    dim3 grid(WWD / TILE_W, HH / TILE_H, B);
    ahpf_fused_kernel<<<grid, 256, SMEM_BYTES>>>(x, Wt, bs, out);
}